// round 13
// baseline (speedup 1.0000x reference)
#include <cuda_runtime.h>
#include <cuda_fp16.h>
#include <cstdint>

#define BATCH   2048
#define IN_DIM  1024
#define HID     512
#define FEAT    256
#define THREADS 128

// ---------------------------------------------------------------------------
// helpers
// ---------------------------------------------------------------------------
__device__ __forceinline__ uint32_t smem_u32(const void* p) {
    uint32_t a;
    asm("{ .reg .u64 t; cvta.to.shared.u64 t, %1; cvt.u32.u64 %0, t; }"
        : "=r"(a) : "l"(p));
    return a;
}
__device__ __forceinline__ void mma16816(float* c, const uint32_t* a, const uint32_t* b)
{
    asm volatile(
        "mma.sync.aligned.m16n8k16.row.col.f32.f16.f16.f32 "
        "{%0,%1,%2,%3}, {%4,%5,%6,%7}, {%8,%9}, {%0,%1,%2,%3};\n"
        : "+f"(c[0]), "+f"(c[1]), "+f"(c[2]), "+f"(c[3])
        : "r"(a[0]), "r"(a[1]), "r"(a[2]), "r"(a[3]), "r"(b[0]), "r"(b[1]));
}
#define LDSM4(r0, r1, r2, r3, addr)                                            \
    asm volatile("ldmatrix.sync.aligned.m8n8.x4.shared.b16 {%0,%1,%2,%3}, [%4];" \
        : "=r"(r0), "=r"(r1), "=r"(r2), "=r"(r3) : "r"(addr))
#define CP16(dst, src)                                                         \
    asm volatile("cp.async.cg.shared.global [%0], [%1], 16;"                   \
        :: "r"(dst), "l"(src))
#define CP_COMMIT() asm volatile("cp.async.commit_group;" ::: "memory")
#define CP_WAIT1()  asm volatile("cp.async.wait_group 1;" ::: "memory")
#define CP_WAIT0()  asm volatile("cp.async.wait_group 0;" ::: "memory")

// ---------------------------- scratch ---------------------------------------
__device__ __align__(16) __half g_X[2 * BATCH * IN_DIM];
__device__ __align__(16) __half g_Wf[HID * IN_DIM];
__device__ __align__(16) __half g_Wb[2 * FEAT * HID];
__device__ __align__(16) __half g_Wo[2 * FEAT * FEAT];
__device__ __align__(16) __half g_H[2 * BATCH * HID];
__device__ __align__(16) __half g_F0[BATCH * FEAT];
__device__ __align__(16) float  g_F1[BATCH * FEAT];

// sync/counters (memset to 0 each launch)
//  [0]=ticket [1]=wf [2]=wb [3]=wo [4]=oi
//  [8..135]   xflag per (z*64+m)
//  [136..263] hcnt  per (z*64+m)   (4 needed)
//  [264..391] fcnt  per (z*64+m)   (4 needed)
__device__ int g_sync[512];
#define IDX_TICKET 0
#define IDX_WF 1
#define IDX_WB 2
#define IDX_WO 3
#define IDX_OI 4
#define IDX_XF 8
#define IDX_H  136
#define IDX_F  264

// tile-count layout
#define N_XC 128
#define N_WF 512
#define N_WB 256
#define N_WO 64
#define N_OI 4
#define P0_END   (N_XC + N_WF + N_WB + N_WO + N_OI)   // 964
#define P1_END   (P0_END + 512)                        // 1476
#define P2_END   (P1_END + 512)                        // 1988
#define P3_END   (P2_END + 512)                        // 2500

// ---------------------------------------------------------------------------
// sync primitives
// ---------------------------------------------------------------------------
__device__ __forceinline__ void wait_ge(int idx, int need, int tid) {
    if (tid == 0) {
        int v;
        for (;;) {
            asm volatile("ld.acquire.gpu.global.s32 %0, [%1];"
                         : "=r"(v) : "l"(g_sync + idx));
            if (v >= need) break;
            __nanosleep(64);
        }
    }
    __syncthreads();
    __threadfence();   // acquire for all threads' subsequent loads
}
__device__ __forceinline__ void signal_add(int idx, int tid) {
    __threadfence();   // release all threads' prior writes
    __syncthreads();
    if (tid == 0) atomicAdd(g_sync + idx, 1);
}

// ---------------------------------------------------------------------------
// GEMM tile body.  BM=32 rows, BK=64 halves/stage, 128 threads, double buffer.
// MODE 0: K1 (bias+relu -> fp16 H)   BN=128, KK=1024, NOUT=512
// MODE 1: K2 (bias; z0 -> fp16 F0, z1 -> fp32 F1)  BN=64, KK=512, NOUT=256
// MODE 2: K3+K4 (dot with F1, atomicAdd into out)  BN=64, KK=256, NOUT=256
// ---------------------------------------------------------------------------
template <int BN, int KK, int NOUT, int MODE>
__device__ void gemm_tile(char* dsm, int tid, int rowBlock, int colBlock, int z,
                          const __half* __restrict__ A, const __half* __restrict__ B,
                          const float* __restrict__ bias,
                          __half* __restrict__ Oh, float* __restrict__ Of,
                          const float* __restrict__ F1p, float* __restrict__ outp)
{
    constexpr int BM   = 32;
    constexpr int BK   = 64;
    constexpr int CHNK = BK / 8;              // 8
    constexpr int ROWB = BK * 2 + 16;         // 144
    constexpr int T    = KK / BK;
    constexpr int WN_W = (BN == 128) ? 4 : 2;
    constexpr int WM_W = 4 / WN_W;
    constexpr int WTM  = BM / WM_W;
    constexpr int WTN  = BN / WN_W;
    constexpr int MI   = WTM / 16;
    constexpr int NI   = WTN / 8;
    constexpr int STAGE = (BM + BN) * ROWB;

    const uint32_t sbase = smem_u32(dsm);
    const int lane = tid & 31;
    const int warp = tid >> 5;
    const int wm = warp / WN_W, wn = warp % WN_W;

    auto stage = [&](int t, int buf_i) {
        const int kt = t * BK;
        const uint32_t buf = sbase + buf_i * STAGE;
        #pragma unroll
        for (int i = 0; i < BM * CHNK / THREADS; i++) {
            int slot = tid + i * THREADS;
            int row = slot / CHNK, ch = slot % CHNK;
            CP16(buf + row * ROWB + ch * 16,
                 A + (size_t)(rowBlock + row) * KK + kt + ch * 8);
        }
        #pragma unroll
        for (int i = 0; i < BN * CHNK / THREADS; i++) {
            int slot = tid + i * THREADS;
            int row = slot / CHNK, ch = slot % CHNK;
            CP16(buf + (BM + row) * ROWB + ch * 16,
                 B + (size_t)(colBlock + row) * KK + kt + ch * 8);
        }
        CP_COMMIT();
    };

    float acc[MI][NI][4];
    #pragma unroll
    for (int mi = 0; mi < MI; mi++)
        #pragma unroll
        for (int ni = 0; ni < NI; ni++)
            #pragma unroll
            for (int r = 0; r < 4; r++) acc[mi][ni][r] = 0.0f;

    const uint32_t aOff = (uint32_t)((wm * WTM + (lane & 15)) * ROWB + (lane >> 4) * 16);
    const uint32_t bOff = (uint32_t)((wn * WTN + ((lane >> 4) << 3) + (lane & 7)) * ROWB
                                     + ((lane >> 3) & 1) * 16);

    stage(0, 0);
    if (T > 1) stage(1, 1);

    #pragma unroll 1
    for (int t = 0; t < T; t++) {
        if (t + 1 < T) { CP_WAIT1(); } else { CP_WAIT0(); }
        __syncthreads();

        const uint32_t buf = sbase + (t & 1) * STAGE;
        const uint32_t aB = buf + aOff;
        const uint32_t bB = buf + BM * ROWB + bOff;

        #pragma unroll
        for (int ks = 0; ks < BK / 16; ks++) {
            const uint32_t ko = ks * 32;
            uint32_t ah[MI][4];
            #pragma unroll
            for (int mi = 0; mi < MI; mi++)
                LDSM4(ah[mi][0], ah[mi][1], ah[mi][2], ah[mi][3],
                      aB + mi * 16 * ROWB + ko);
            uint32_t bh[NI][2];
            #pragma unroll
            for (int np = 0; np < NI / 2; np++)
                LDSM4(bh[np * 2][0], bh[np * 2][1], bh[np * 2 + 1][0], bh[np * 2 + 1][1],
                      bB + np * 16 * ROWB + ko);
            #pragma unroll
            for (int mi = 0; mi < MI; mi++)
                #pragma unroll
                for (int ni = 0; ni < NI; ni++)
                    mma16816(acc[mi][ni], ah[mi], bh[ni]);
        }
        if (t + 2 < T) {
            __syncthreads();
            stage(t + 2, t & 1);
        }
    }

    const int g  = lane >> 2;
    const int kq = lane & 3;
    #pragma unroll
    for (int mi = 0; mi < MI; mi++) {
        #pragma unroll
        for (int half = 0; half < 2; half++) {
            const int grow = rowBlock + wm * WTM + mi * 16 + half * 8 + g;
            if (MODE == 2) {
                float s = 0.0f;
                #pragma unroll
                for (int ni = 0; ni < NI; ni++) {
                    const int gc = colBlock + wn * WTN + ni * 8 + kq * 2;
                    float2 fv = *reinterpret_cast<const float2*>(
                        F1p + (size_t)grow * FEAT + gc);
                    s = fmaf(acc[mi][ni][half * 2 + 0], fv.x,
                        fmaf(acc[mi][ni][half * 2 + 1], fv.y, s));
                }
                s += __shfl_xor_sync(0xFFFFFFFFu, s, 1);
                s += __shfl_xor_sync(0xFFFFFFFFu, s, 2);
                if (kq == 0) atomicAdd(&outp[grow * 2 + z], s);
            } else {
                #pragma unroll
                for (int ni = 0; ni < NI; ni++) {
                    const int gc = colBlock + wn * WTN + ni * 8 + kq * 2;
                    float v0 = acc[mi][ni][half * 2 + 0] + bias[gc];
                    float v1 = acc[mi][ni][half * 2 + 1] + bias[gc + 1];
                    if (MODE == 0) { v0 = fmaxf(v0, 0.0f); v1 = fmaxf(v1, 0.0f); }
                    const size_t base = (size_t)grow * NOUT + gc;
                    if (MODE == 0 || z == 0) {
                        *reinterpret_cast<__half2*>(Oh + base) =
                            __halves2half2(__float2half(v0), __float2half(v1));
                    } else {
                        *reinterpret_cast<float2*>(Of + base) = make_float2(v0, v1);
                    }
                }
            }
        }
    }
    __syncthreads();   // smem safe for next tile
}

// 32x32 fp32->fp16 transpose tile (128 threads)
__device__ void transpose_tile(char* dsm, int tid,
                               const float* __restrict__ W, __half* __restrict__ hi,
                               int Krows, int Ncols, int bxn, int byk)
{
    float (*tile)[33] = reinterpret_cast<float (*)[33]>(dsm);
    int tx = tid & 31, ty = tid >> 5;         // 32 x 4
    int n0 = bxn * 32, k0 = byk * 32;
    #pragma unroll
    for (int i = 0; i < 32; i += 4)
        tile[ty + i][tx] = W[(size_t)(k0 + ty + i) * Ncols + n0 + tx];
    __syncthreads();
    #pragma unroll
    for (int i = 0; i < 32; i += 4)
        hi[(size_t)(n0 + ty + i) * Krows + k0 + tx] = __float2half(tile[tx][ty + i]);
    __syncthreads();
}

// ---------------------------------------------------------------------------
// the persistent mega-kernel
// ---------------------------------------------------------------------------
__global__ void __launch_bounds__(THREADS, 2)
mega_kernel(const float* __restrict__ x0, const float* __restrict__ x1,
            const float* __restrict__ W_feat, const float* __restrict__ b_feat,
            const float* __restrict__ W_br0,  const float* __restrict__ b_br0,
            const float* __restrict__ W_br1,  const float* __restrict__ b_br1,
            const float* __restrict__ W_out,  const float* __restrict__ b_out,
            float* __restrict__ out)
{
    extern __shared__ char dsm[];
    const int tid = threadIdx.x;
    __shared__ int s_ticket;

    for (;;) {
        if (tid == 0) s_ticket = atomicAdd(&g_sync[IDX_TICKET], 1);
        __syncthreads();
        const int tk = s_ticket;
        __syncthreads();
        if (tk >= P3_END) break;

        if (tk < N_XC) {
            // ---- x -> fp16, one 32-row block ----
            int z = tk >> 6, m = tk & 63;
            const float* src = z ? x1 : x0;
            __half* dst = g_X + (size_t)z * BATCH * IN_DIM;
            int base4 = m * (32 * IN_DIM / 4);           // float4 index
            #pragma unroll
            for (int q = 0; q < 64; q++) {
                int i = base4 + tid + q * THREADS;
                float4 v = reinterpret_cast<const float4*>(src)[i];
                __half2* hp = reinterpret_cast<__half2*>(dst) + (size_t)i * 2;
                hp[0] = __halves2half2(__float2half(v.x), __float2half(v.y));
                hp[1] = __halves2half2(__float2half(v.z), __float2half(v.w));
            }
            signal_add(IDX_XF + tk, tid);
        } else if (tk < N_XC + N_WF) {
            int t = tk - N_XC;                            // 16 n x 32 k
            transpose_tile(dsm, tid, W_feat, g_Wf, IN_DIM, HID, t & 15, t >> 4);
            signal_add(IDX_WF, tid);
        } else if (tk < N_XC + N_WF + N_WB) {
            int t = tk - (N_XC + N_WF);
            int zz = t >> 7; t &= 127;                    // 8 n x 16 k
            transpose_tile(dsm, tid, zz ? W_br1 : W_br0,
                           g_Wb + (size_t)zz * FEAT * HID, HID, FEAT, t & 7, t >> 3);
            signal_add(IDX_WB, tid);
        } else if (tk < N_XC + N_WF + N_WB + N_WO) {
            int t = tk - (N_XC + N_WF + N_WB);
            int r = t * 1024 + tid * 8;                   // float2 index
            #pragma unroll
            for (int q = 0; q < 8; q++) {
                float2 w = reinterpret_cast<const float2*>(W_out)[r + q];
                g_Wo[r + q]               = __float2half(w.x);
                g_Wo[FEAT * FEAT + r + q] = __float2half(w.y);
            }
            signal_add(IDX_WO, tid);
        } else if (tk < P0_END) {
            int t = tk - (N_XC + N_WF + N_WB + N_WO);
            int i = t * 1024 + tid * 8;
            float b0 = b_out[0], b1 = b_out[1];
            #pragma unroll
            for (int q = 0; q < 8; q++) out[i + q] = ((i + q) & 1) ? b1 : b0;
            signal_add(IDX_OI, tid);
        } else if (tk < P1_END) {
            // ---- K1: H = relu(x @ Wf + b_feat) ----
            int t = tk - P0_END;                          // m*8 + n*2 + z
            int m = t >> 3, n = (t >> 1) & 3, z = t & 1;
            wait_ge(IDX_WF, N_WF, tid);
            wait_ge(IDX_XF + z * 64 + m, 1, tid);
            gemm_tile<128, IN_DIM, HID, 0>(
                dsm, tid, m * 32, n * 128, z,
                g_X + (size_t)z * BATCH * IN_DIM, g_Wf, b_feat,
                g_H + (size_t)z * BATCH * HID, nullptr, nullptr, nullptr);
            signal_add(IDX_H + z * 64 + m, tid);
        } else if (tk < P2_END) {
            // ---- K2: F_z = H_z @ Wb_z + b ----
            int t = tk - P1_END;
            int m = t >> 3, n = (t >> 1) & 3, z = t & 1;
            wait_ge(IDX_WB, N_WB, tid);
            wait_ge(IDX_H + z * 64 + m, 4, tid);
            gemm_tile<64, HID, FEAT, 1>(
                dsm, tid, m * 32, n * 64, z,
                g_H + (size_t)z * BATCH * HID, g_Wb + (size_t)z * FEAT * HID,
                z ? b_br1 : b_br0, g_F0, g_F1, nullptr, nullptr);
            signal_add(IDX_F + z * 64 + m, tid);
        } else {
            // ---- K3+K4: out[b,z] += <F1[b,:], (F0 @ Wo_z^T)[b,:]> ----
            int t = tk - P2_END;
            int m = t >> 3, n = (t >> 1) & 3, z = t & 1;
            wait_ge(IDX_WO, N_WO, tid);
            wait_ge(IDX_OI, N_OI, tid);
            wait_ge(IDX_F + m, 4, tid);
            wait_ge(IDX_F + 64 + m, 4, tid);
            gemm_tile<64, FEAT, FEAT, 2>(
                dsm, tid, m * 32, n * 64, z,
                g_F0, g_Wo + (size_t)z * FEAT * FEAT, nullptr,
                nullptr, nullptr, g_F1, out);
        }
    }
}

// ---------------------------- launch ----------------------------------------
extern "C" void kernel_launch(void* const* d_in, const int* in_sizes, int n_in,
                              void* d_out, int out_size)
{
    const float* x0     = (const float*)d_in[0];
    const float* x1     = (const float*)d_in[1];
    const float* W_feat = (const float*)d_in[2];
    const float* b_feat = (const float*)d_in[3];
    const float* W_br0  = (const float*)d_in[4];
    const float* b_br0  = (const float*)d_in[5];
    const float* W_br1  = (const float*)d_in[6];
    const float* b_br1  = (const float*)d_in[7];
    const float* W_out  = (const float*)d_in[8];
    const float* b_out  = (const float*)d_in[9];
    float*       out    = (float*)d_out;

    // zero counters (memset node — capturable, no allocation)
    void* syncPtr = nullptr;
    cudaGetSymbolAddress(&syncPtr, g_sync);
    cudaMemsetAsync(syncPtr, 0, sizeof(g_sync));

    // smem: K1 stage (32+128)*144 = 23040, x2 = 46080
    constexpr int SMEM_DYN = 2 * (32 + 128) * 144;
    static int ncta = 0;
    int dev, sms;
    cudaGetDevice(&dev);
    cudaDeviceGetAttribute(&sms, cudaDevAttrMultiProcessorCount, dev);
    ncta = 2 * sms;
    cudaFuncSetAttribute((const void*)mega_kernel,
                         cudaFuncAttributeMaxDynamicSharedMemorySize, SMEM_DYN);

    mega_kernel<<<ncta, THREADS, SMEM_DYN>>>(
        x0, x1, W_feat, b_feat, W_br0, b_br0, W_br1, b_br1, W_out, b_out, out);
}

// round 14
// speedup vs baseline: 1.3383x; 1.3383x over previous
#include <cuda_runtime.h>
#include <cuda_fp16.h>
#include <cstdint>

#define BATCH   2048
#define IN_DIM  1024
#define HID     512
#define FEAT    256

// ---------------------------------------------------------------------------
// helpers
// ---------------------------------------------------------------------------
__device__ __forceinline__ uint32_t smem_u32(const void* p) {
    uint32_t a;
    asm("{ .reg .u64 t; cvta.to.shared.u64 t, %1; cvt.u32.u64 %0, t; }"
        : "=r"(a) : "l"(p));
    return a;
}

__device__ __forceinline__ void mma16816(float* c, const uint32_t* a, const uint32_t* b)
{
    asm volatile(
        "mma.sync.aligned.m16n8k16.row.col.f32.f16.f16.f32 "
        "{%0,%1,%2,%3}, {%4,%5,%6,%7}, {%8,%9}, {%0,%1,%2,%3};\n"
        : "+f"(c[0]), "+f"(c[1]), "+f"(c[2]), "+f"(c[3])
        : "r"(a[0]), "r"(a[1]), "r"(a[2]), "r"(a[3]), "r"(b[0]), "r"(b[1]));
}

#define LDSM4(r0, r1, r2, r3, addr)                                            \
    asm volatile("ldmatrix.sync.aligned.m8n8.x4.shared.b16 {%0,%1,%2,%3}, [%4];" \
        : "=r"(r0), "=r"(r1), "=r"(r2), "=r"(r3) : "r"(addr))

#define CP16(dst, src)                                                         \
    asm volatile("cp.async.cg.shared.global [%0], [%1], 16;"                   \
        :: "r"(dst), "l"(src))
#define CP_COMMIT() asm volatile("cp.async.commit_group;" ::: "memory")
#define CP_WAIT1()  asm volatile("cp.async.wait_group 1;" ::: "memory")
#define CP_WAIT0()  asm volatile("cp.async.wait_group 0;" ::: "memory")

// ---------------------------- scratch ---------------------------------------
__device__ __align__(16) __half g_X[2 * BATCH * IN_DIM];      // fp16 x
__device__ __align__(16) __half g_Wf[HID * IN_DIM];           // [N=512][K=1024]
__device__ __align__(16) __half g_Wb[2 * FEAT * HID];         // [z][N=256][K=512]
__device__ __align__(16) __half g_Wo[2 * FEAT * FEAT];        // [o][j][i]
__device__ __align__(16) __half g_H[2 * BATCH * HID];
__device__ __align__(16) __half g_F0[BATCH * FEAT];
__device__ __align__(16) float  g_F1[BATCH * FEAT];

// ---------------------------------------------------------------------------
// fp16 mma.sync GEMM, BK=128 double buffer (identical math to the 41.8us
// kernel).  PDL: when PREB=1, the B (weight) operand of stage 0 is staged
// BEFORE cudaGridDependencySynchronize() — it comes from prep, already
// visible — and the dependent A operand after.  Group order (B0, A0, S1, ...)
// keeps the WAIT1/WAIT0 stage logic valid with one extra in-flight group.
// MODE 0: K1 (bias+relu, fp16 out)     PREB=0 (both operands from prep)
// MODE 1: K2 (bias; z0->F0, z1->F1)    PREB=1
// MODE 2: K3 (fused final dot)         PREB=1
// ---------------------------------------------------------------------------
template <int BM, int BN, int THREADS, int KK, int NOUT, int MODE, int MINB, int PREB>
__global__ void __launch_bounds__(THREADS, MINB)
gemm_mma(const __half* __restrict__ A, const __half* __restrict__ B,
         const float* __restrict__ bias0, const float* __restrict__ bias1,
         __half* __restrict__ Oh, float* __restrict__ Ofa, float* __restrict__ Ofb)
{
    constexpr int BK   = 128;
    constexpr int CHNK = BK / 8;              // 16
    constexpr int ROWB = BK * 2 + 16;         // 272
    constexpr int T    = KK / BK;
    constexpr int WARPS = THREADS / 32;
    constexpr int WN_W = (BN == 128) ? 4 : 2;
    constexpr int WM_W = WARPS / WN_W;
    constexpr int WTM  = BM / WM_W;
    constexpr int WTN  = BN / WN_W;
    constexpr int MI   = WTM / 16;
    constexpr int NI   = WTN / 8;
    constexpr int STAGE = (BM + BN) * ROWB;
    constexpr size_t AZ = (MODE == 0) ? (size_t)BATCH * IN_DIM
                         : (MODE == 1) ? (size_t)BATCH * HID : 0;
    constexpr size_t BZ = (MODE == 0) ? 0
                         : (MODE == 1) ? (size_t)FEAT * HID : (size_t)FEAT * FEAT;
    constexpr size_t OZ = (size_t)BATCH * NOUT;

    extern __shared__ char dsm[];
    const uint32_t sbase = smem_u32(dsm);

    const int tid  = threadIdx.x;
    const int lane = tid & 31;
    const int warp = tid >> 5;
    const int wm = warp / WN_W, wn = warp % WN_W;
    const int z = blockIdx.z;
    const int rowBlock = blockIdx.y * BM;
    const int colBlock = blockIdx.x * BN;

    A += (size_t)z * AZ;
    B += (size_t)z * BZ;
    const float* bias = z ? bias1 : bias0;

    auto stageA = [&](int t, int buf_i) {
        const int kt = t * BK;
        const uint32_t buf = sbase + buf_i * STAGE;
        #pragma unroll
        for (int i = 0; i < BM * CHNK / THREADS; i++) {
            int slot = tid + i * THREADS;
            int row = slot / CHNK, ch = slot % CHNK;
            CP16(buf + row * ROWB + ch * 16,
                 A + (size_t)(rowBlock + row) * KK + kt + ch * 8);
        }
    };
    auto stageB = [&](int t, int buf_i) {
        const int kt = t * BK;
        const uint32_t buf = sbase + buf_i * STAGE;
        #pragma unroll
        for (int i = 0; i < BN * CHNK / THREADS; i++) {
            int slot = tid + i * THREADS;
            int row = slot / CHNK, ch = slot % CHNK;
            CP16(buf + (BM + row) * ROWB + ch * 16,
                 B + (size_t)(colBlock + row) * KK + kt + ch * 8);
        }
    };

    // ----- PDL prologue -----
    if (PREB) {
        stageB(0, 0);           // weights: visible before predecessor GEMM
        CP_COMMIT();
        cudaGridDependencySynchronize();
        stageA(0, 0);           // dependent activations
        CP_COMMIT();
    } else {
        cudaGridDependencySynchronize();
        stageA(0, 0);
        stageB(0, 0);
        CP_COMMIT();
    }
    if (T > 1) { stageA(1, 1); stageB(1, 1); CP_COMMIT(); }

    float acc[MI][NI][4];
    #pragma unroll
    for (int mi = 0; mi < MI; mi++)
        #pragma unroll
        for (int ni = 0; ni < NI; ni++)
            #pragma unroll
            for (int r = 0; r < 4; r++) acc[mi][ni][r] = 0.0f;

    const uint32_t aOff = (uint32_t)((wm * WTM + (lane & 15)) * ROWB + (lane >> 4) * 16);
    const uint32_t bOff = (uint32_t)((wn * WTN + ((lane >> 4) << 3) + (lane & 7)) * ROWB
                                     + ((lane >> 3) & 1) * 16);

    #pragma unroll 1
    for (int t = 0; t < T; t++) {
        if (t + 1 < T) { CP_WAIT1(); } else { CP_WAIT0(); }
        __syncthreads();

        const uint32_t buf = sbase + (t & 1) * STAGE;
        const uint32_t aB = buf + aOff;
        const uint32_t bB = buf + BM * ROWB + bOff;

        #pragma unroll
        for (int ks = 0; ks < BK / 16; ks++) {
            const uint32_t ko = ks * 32;
            uint32_t ah[MI][4];
            #pragma unroll
            for (int mi = 0; mi < MI; mi++)
                LDSM4(ah[mi][0], ah[mi][1], ah[mi][2], ah[mi][3],
                      aB + mi * 16 * ROWB + ko);
            uint32_t bh[NI][2];
            #pragma unroll
            for (int np = 0; np < NI / 2; np++)
                LDSM4(bh[np * 2][0], bh[np * 2][1], bh[np * 2 + 1][0], bh[np * 2 + 1][1],
                      bB + np * 16 * ROWB + ko);
            #pragma unroll
            for (int mi = 0; mi < MI; mi++)
                #pragma unroll
                for (int ni = 0; ni < NI; ni++)
                    mma16816(acc[mi][ni], ah[mi], bh[ni]);
        }

        if (t + 2 < T) {
            __syncthreads();
            stageA(t + 2, t & 1);
            stageB(t + 2, t & 1);
            CP_COMMIT();
        }
    }

    // ------------------------------ epilogue --------------------------------
    const int g  = lane >> 2;
    const int kq = lane & 3;
    #pragma unroll
    for (int mi = 0; mi < MI; mi++) {
        #pragma unroll
        for (int half = 0; half < 2; half++) {
            const int grow = rowBlock + wm * WTM + mi * 16 + half * 8 + g;
            if (MODE == 2) {
                const float* F1p = Ofa;
                float s = 0.0f;
                #pragma unroll
                for (int ni = 0; ni < NI; ni++) {
                    const int gc = colBlock + wn * WTN + ni * 8 + kq * 2;
                    float2 fv = *reinterpret_cast<const float2*>(
                        F1p + (size_t)grow * FEAT + gc);
                    s = fmaf(acc[mi][ni][half * 2 + 0], fv.x,
                        fmaf(acc[mi][ni][half * 2 + 1], fv.y, s));
                }
                s += __shfl_xor_sync(0xFFFFFFFFu, s, 1);
                s += __shfl_xor_sync(0xFFFFFFFFu, s, 2);
                if (kq == 0) atomicAdd(&Ofb[grow * 2 + z], s);
            } else {
                #pragma unroll
                for (int ni = 0; ni < NI; ni++) {
                    const int gc = colBlock + wn * WTN + ni * 8 + kq * 2;
                    float v0 = acc[mi][ni][half * 2 + 0] + bias[gc];
                    float v1 = acc[mi][ni][half * 2 + 1] + bias[gc + 1];
                    if (MODE == 0) { v0 = fmaxf(v0, 0.0f); v1 = fmaxf(v1, 0.0f); }
                    const size_t base = (size_t)grow * NOUT + gc;
                    if (MODE == 0 || z == 0) {
                        __half* oh = Oh;
                        if (MODE == 0) oh += (size_t)z * OZ;
                        *reinterpret_cast<__half2*>(oh + base) =
                            __halves2half2(__float2half(v0), __float2half(v1));
                    } else {
                        *reinterpret_cast<float2*>(Ofa + base) = make_float2(v0, v1);
                    }
                }
            }
        }
    }
    // let the dependent kernel start its prologue while we drain
    cudaTriggerProgrammaticLaunchCompletion();
}

// ---------------------------------------------------------------------------
// Unified prep kernel (identical to the 41.8us version) + PDL trigger
// ---------------------------------------------------------------------------
#define XB 2048
#define WF_TILES 512
#define WB_TILES 256
#define WO_BLKS 64
#define OI_BLKS 4

__device__ __forceinline__ void transpose_tile(
    const float* __restrict__ W, __half* __restrict__ hi,
    int Krows, int Ncols, int bxn, int byk, float (*tile)[33], int tid)
{
    int tx = tid & 31, ty = tid >> 5;
    int n0 = bxn * 32, k0 = byk * 32;
    #pragma unroll
    for (int i = 0; i < 32; i += 8)
        tile[ty + i][tx] = W[(size_t)(k0 + ty + i) * Ncols + n0 + tx];
    __syncthreads();
    #pragma unroll
    for (int i = 0; i < 32; i += 8)
        hi[(size_t)(n0 + ty + i) * Krows + k0 + tx] = __float2half(tile[tx][ty + i]);
}

__global__ void __launch_bounds__(256)
prep_kernel(const float* __restrict__ x0, const float* __restrict__ x1,
            const float* __restrict__ W_feat,
            const float* __restrict__ W_br0, const float* __restrict__ W_br1,
            const float* __restrict__ W_out, const float* __restrict__ b_out,
            __half* __restrict__ X,
            __half* __restrict__ Wf, __half* __restrict__ Wb,
            __half* __restrict__ Wo, float* __restrict__ out)
{
    __shared__ float tile[32][33];
    const int tid = threadIdx.x;
    int bx = blockIdx.x;

    if (bx < 2 * XB) {
        const float* src = (bx < XB) ? x0 : x1;
        size_t zoff = (bx < XB) ? 0 : (size_t)BATCH * IN_DIM;
        int i = (bx & (XB - 1)) * 256 + tid;
        float4 v = reinterpret_cast<const float4*>(src)[i];
        __half2* hp = reinterpret_cast<__half2*>(X + zoff) + (size_t)i * 2;
        hp[0] = __halves2half2(__float2half(v.x), __float2half(v.y));
        hp[1] = __halves2half2(__float2half(v.z), __float2half(v.w));
    } else if (bx < 2 * XB + WF_TILES) {
        int t = bx - 2 * XB;
        transpose_tile(W_feat, Wf, IN_DIM, HID, t & 15, t >> 4, tile, tid);
    } else if (bx < 2 * XB + WF_TILES + WB_TILES) {
        int t = bx - (2 * XB + WF_TILES);
        int zz = t >> 7; t &= 127;
        transpose_tile(zz ? W_br1 : W_br0, Wb + (size_t)zz * FEAT * HID,
                       HID, FEAT, t & 7, t >> 3, tile, tid);
    } else if (bx < 2 * XB + WF_TILES + WB_TILES + WO_BLKS) {
        int t = bx - (2 * XB + WF_TILES + WB_TILES);
        int r = t * 1024 + tid * 4;
        #pragma unroll
        for (int q = 0; q < 4; q++) {
            float2 w = reinterpret_cast<const float2*>(W_out)[r + q];
            Wo[r + q]               = __float2half(w.x);
            Wo[FEAT * FEAT + r + q] = __float2half(w.y);
        }
    } else {
        int t = bx - (2 * XB + WF_TILES + WB_TILES + WO_BLKS);
        int i = t * 1024 + tid * 4;
        float b0 = b_out[0], b1 = b_out[1];
        #pragma unroll
        for (int q = 0; q < 4; q++) out[i + q] = ((i + q) & 1) ? b1 : b0;
    }
    cudaTriggerProgrammaticLaunchCompletion();
}

// ---------------------------- launch ----------------------------------------
extern "C" void kernel_launch(void* const* d_in, const int* in_sizes, int n_in,
                              void* d_out, int out_size)
{
    const float* x0     = (const float*)d_in[0];
    const float* x1     = (const float*)d_in[1];
    const float* W_feat = (const float*)d_in[2];
    const float* b_feat = (const float*)d_in[3];
    const float* W_br0  = (const float*)d_in[4];
    const float* b_br0  = (const float*)d_in[5];
    const float* W_br1  = (const float*)d_in[6];
    const float* b_br1  = (const float*)d_in[7];
    const float* W_out  = (const float*)d_in[8];
    const float* b_out  = (const float*)d_in[9];
    float*       out    = (float*)d_out;

    __half *X, *Wf, *Wb, *Wo, *H, *F0;
    float *F1;
    cudaGetSymbolAddress((void**)&X, g_X);
    cudaGetSymbolAddress((void**)&Wf, g_Wf);
    cudaGetSymbolAddress((void**)&Wb, g_Wb);
    cudaGetSymbolAddress((void**)&Wo, g_Wo);
    cudaGetSymbolAddress((void**)&H, g_H);
    cudaGetSymbolAddress((void**)&F0, g_F0);
    cudaGetSymbolAddress((void**)&F1, g_F1);

    constexpr int SM1 = 2 * (64 + 128) * 272;    // 104448
    constexpr int SM2 = 2 * (32 + 64) * 272;     //  52224

    auto k1 = gemm_mma<64, 128, 256, 1024, 512, 0, 2, 0>;
    auto k2 = gemm_mma<32, 64, 128, 512, 256, 1, 4, 1>;
    auto k3 = gemm_mma<32, 64, 128, 256, 256, 2, 4, 1>;

    cudaFuncSetAttribute((const void*)k1, cudaFuncAttributeMaxDynamicSharedMemorySize, SM1);
    cudaFuncSetAttribute((const void*)k2, cudaFuncAttributeMaxDynamicSharedMemorySize, SM2);
    cudaFuncSetAttribute((const void*)k3, cudaFuncAttributeMaxDynamicSharedMemorySize, SM2);

    // prep (plain launch, first in stream)
    prep_kernel<<<2 * XB + WF_TILES + WB_TILES + WO_BLKS + OI_BLKS, 256>>>(
        x0, x1, W_feat, W_br0, W_br1, W_out, b_out, X, Wf, Wb, Wo, out);

    // PDL attribute shared by the three GEMM launches
    cudaLaunchAttribute attr[1];
    attr[0].id = cudaLaunchAttributeProgrammaticStreamSerialization;
    attr[0].val.programmaticStreamSerializationAllowed = 1;

    {   // K1: grid (4, 32, 2) = 256 CTAs x 8 warps
        cudaLaunchConfig_t cfg{};
        cfg.gridDim  = dim3(HID / 128, BATCH / 64, 2);
        cfg.blockDim = dim3(256, 1, 1);
        cfg.dynamicSmemBytes = SM1;
        cfg.stream = 0;
        cfg.attrs = attr;
        cfg.numAttrs = 1;
        cudaLaunchKernelEx(&cfg, k1, X, Wf, b_feat, b_feat, H,
                           (float*)nullptr, (float*)nullptr);
    }
    {   // K2: grid (4, 64, 2) = 512 CTAs x 4 warps
        cudaLaunchConfig_t cfg{};
        cfg.gridDim  = dim3(FEAT / 64, BATCH / 32, 2);
        cfg.blockDim = dim3(128, 1, 1);
        cfg.dynamicSmemBytes = SM2;
        cfg.stream = 0;
        cfg.attrs = attr;
        cfg.numAttrs = 1;
        cudaLaunchKernelEx(&cfg, k2, H, Wb, b_br0, b_br1, F0, F1,
                           (float*)nullptr);
    }
    {   // K3 (+fused K4): 512 CTAs x 4 warps
        cudaLaunchConfig_t cfg{};
        cfg.gridDim  = dim3(FEAT / 64, BATCH / 32, 2);
        cfg.blockDim = dim3(128, 1, 1);
        cfg.dynamicSmemBytes = SM2;
        cfg.stream = 0;
        cfg.attrs = attr;
        cfg.numAttrs = 1;
        cudaLaunchKernelEx(&cfg, k3, F0, Wo, (const float*)nullptr,
                           (const float*)nullptr, (__half*)nullptr, F1, out);
    }
}

// round 15
// speedup vs baseline: 1.4207x; 1.0616x over previous
#include <cuda_runtime.h>
#include <cuda_fp16.h>
#include <cstdint>

#define BATCH   2048
#define IN_DIM  1024
#define HID     512
#define FEAT    256

// ---------------------------------------------------------------------------
// helpers
// ---------------------------------------------------------------------------
__device__ __forceinline__ uint32_t smem_u32(const void* p) {
    uint32_t a;
    asm("{ .reg .u64 t; cvta.to.shared.u64 t, %1; cvt.u32.u64 %0, t; }"
        : "=r"(a) : "l"(p));
    return a;
}

__device__ __forceinline__ void mma16816(float* c, const uint32_t* a, const uint32_t* b)
{
    asm volatile(
        "mma.sync.aligned.m16n8k16.row.col.f32.f16.f16.f32 "
        "{%0,%1,%2,%3}, {%4,%5,%6,%7}, {%8,%9}, {%0,%1,%2,%3};\n"
        : "+f"(c[0]), "+f"(c[1]), "+f"(c[2]), "+f"(c[3])
        : "r"(a[0]), "r"(a[1]), "r"(a[2]), "r"(a[3]), "r"(b[0]), "r"(b[1]));
}

#define LDSM4(r0, r1, r2, r3, addr)                                            \
    asm volatile("ldmatrix.sync.aligned.m8n8.x4.shared.b16 {%0,%1,%2,%3}, [%4];" \
        : "=r"(r0), "=r"(r1), "=r"(r2), "=r"(r3) : "r"(addr))

#define CP16(dst, src)                                                         \
    asm volatile("cp.async.cg.shared.global [%0], [%1], 16;"                   \
        :: "r"(dst), "l"(src))
#define CP_COMMIT() asm volatile("cp.async.commit_group;" ::: "memory")
#define CP_WAIT1()  asm volatile("cp.async.wait_group 1;" ::: "memory")
#define CP_WAIT0()  asm volatile("cp.async.wait_group 0;" ::: "memory")

// ---------------------------- scratch ---------------------------------------
__device__ __align__(16) __half g_X[2 * BATCH * IN_DIM];      // fp16 x
__device__ __align__(16) __half g_Wf[HID * IN_DIM];           // [N=512][K=1024]
__device__ __align__(16) __half g_Wb[2 * FEAT * HID];         // [z][N=256][K=512]
__device__ __align__(16) __half g_Wo[2 * FEAT * FEAT];        // [o][j][i]
__device__ __align__(16) __half g_H[2 * BATCH * HID];
__device__ __align__(16) __half g_F0[BATCH * FEAT];
__device__ __align__(16) float  g_F1[BATCH * FEAT];

// ---------------------------------------------------------------------------
// fp16 mma.sync GEMM, BK=128 double buffer.  WNW = warps along N.
// All kernels now use warp tiles WTM=32 (MI=2) x WTN=32 (NI=4): 8 MMAs per
// ks-step per warp — enough independent MMAs to cover HMMA latency.
// MODE 0: K1 (bias+relu, fp16 out)
// MODE 1: K2 (bias; z=0 -> fp16 F0, z=1 -> fp32 F1)
// MODE 2: K3 (fused final dot into out via atomics)
// ---------------------------------------------------------------------------
template <int BM, int BN, int THREADS, int KK, int NOUT, int MODE, int MINB, int WNW>
__global__ void __launch_bounds__(THREADS, MINB)
gemm_mma(const __half* __restrict__ A, const __half* __restrict__ B,
         const float* __restrict__ bias0, const float* __restrict__ bias1,
         __half* __restrict__ Oh, float* __restrict__ Ofa, float* __restrict__ Ofb)
{
    constexpr int BK   = 128;
    constexpr int CHNK = BK / 8;              // 16
    constexpr int ROWB = BK * 2 + 16;         // 272
    constexpr int T    = KK / BK;
    constexpr int WARPS = THREADS / 32;
    constexpr int WN_W = WNW;
    constexpr int WM_W = WARPS / WN_W;
    constexpr int WTM  = BM / WM_W;
    constexpr int WTN  = BN / WN_W;
    constexpr int MI   = WTM / 16;
    constexpr int NI   = WTN / 8;
    constexpr int STAGE = (BM + BN) * ROWB;
    constexpr size_t AZ = (MODE == 0) ? (size_t)BATCH * IN_DIM
                         : (MODE == 1) ? (size_t)BATCH * HID : 0;
    constexpr size_t BZ = (MODE == 0) ? 0
                         : (MODE == 1) ? (size_t)FEAT * HID : (size_t)FEAT * FEAT;
    constexpr size_t OZ = (size_t)BATCH * NOUT;

    extern __shared__ char dsm[];
    const uint32_t sbase = smem_u32(dsm);

    const int tid  = threadIdx.x;
    const int lane = tid & 31;
    const int warp = tid >> 5;
    const int wm = warp / WN_W, wn = warp % WN_W;
    const int z = blockIdx.z;
    const int rowBlock = blockIdx.y * BM;
    const int colBlock = blockIdx.x * BN;

    A += (size_t)z * AZ;
    B += (size_t)z * BZ;
    const float* bias = z ? bias1 : bias0;

    auto stage = [&](int t, int buf_i) {
        const int kt = t * BK;
        const uint32_t buf = sbase + buf_i * STAGE;
        #pragma unroll
        for (int i = 0; i < BM * CHNK / THREADS; i++) {
            int slot = tid + i * THREADS;
            int row = slot / CHNK, ch = slot % CHNK;
            CP16(buf + row * ROWB + ch * 16,
                 A + (size_t)(rowBlock + row) * KK + kt + ch * 8);
        }
        #pragma unroll
        for (int i = 0; i < BN * CHNK / THREADS; i++) {
            int slot = tid + i * THREADS;
            int row = slot / CHNK, ch = slot % CHNK;
            CP16(buf + (BM + row) * ROWB + ch * 16,
                 B + (size_t)(colBlock + row) * KK + kt + ch * 8);
        }
        CP_COMMIT();
    };

    float acc[MI][NI][4];
    #pragma unroll
    for (int mi = 0; mi < MI; mi++)
        #pragma unroll
        for (int ni = 0; ni < NI; ni++)
            #pragma unroll
            for (int r = 0; r < 4; r++) acc[mi][ni][r] = 0.0f;

    const uint32_t aOff = (uint32_t)((wm * WTM + (lane & 15)) * ROWB + (lane >> 4) * 16);
    const uint32_t bOff = (uint32_t)((wn * WTN + ((lane >> 4) << 3) + (lane & 7)) * ROWB
                                     + ((lane >> 3) & 1) * 16);

    stage(0, 0);
    if (T > 1) stage(1, 1);

    #pragma unroll 1
    for (int t = 0; t < T; t++) {
        if (t + 1 < T) { CP_WAIT1(); } else { CP_WAIT0(); }
        __syncthreads();

        const uint32_t buf = sbase + (t & 1) * STAGE;
        const uint32_t aB = buf + aOff;
        const uint32_t bB = buf + BM * ROWB + bOff;

        #pragma unroll
        for (int ks = 0; ks < BK / 16; ks++) {
            const uint32_t ko = ks * 32;
            uint32_t ah[MI][4];
            #pragma unroll
            for (int mi = 0; mi < MI; mi++)
                LDSM4(ah[mi][0], ah[mi][1], ah[mi][2], ah[mi][3],
                      aB + mi * 16 * ROWB + ko);
            uint32_t bh[NI][2];
            #pragma unroll
            for (int np = 0; np < NI / 2; np++)
                LDSM4(bh[np * 2][0], bh[np * 2][1], bh[np * 2 + 1][0], bh[np * 2 + 1][1],
                      bB + np * 16 * ROWB + ko);
            #pragma unroll
            for (int mi = 0; mi < MI; mi++)
                #pragma unroll
                for (int ni = 0; ni < NI; ni++)
                    mma16816(acc[mi][ni], ah[mi], bh[ni]);
        }

        if (t + 2 < T) {
            __syncthreads();
            stage(t + 2, t & 1);
        }
    }

    // ------------------------------ epilogue --------------------------------
    const int g  = lane >> 2;
    const int kq = lane & 3;
    #pragma unroll
    for (int mi = 0; mi < MI; mi++) {
        #pragma unroll
        for (int half = 0; half < 2; half++) {
            const int grow = rowBlock + wm * WTM + mi * 16 + half * 8 + g;
            if (MODE == 2) {
                const float* F1p = Ofa;
                float s = 0.0f;
                #pragma unroll
                for (int ni = 0; ni < NI; ni++) {
                    const int gc = colBlock + wn * WTN + ni * 8 + kq * 2;
                    float2 fv = *reinterpret_cast<const float2*>(
                        F1p + (size_t)grow * FEAT + gc);
                    s = fmaf(acc[mi][ni][half * 2 + 0], fv.x,
                        fmaf(acc[mi][ni][half * 2 + 1], fv.y, s));
                }
                s += __shfl_xor_sync(0xFFFFFFFFu, s, 1);
                s += __shfl_xor_sync(0xFFFFFFFFu, s, 2);
                if (kq == 0) atomicAdd(&Ofb[grow * 2 + z], s);
            } else {
                #pragma unroll
                for (int ni = 0; ni < NI; ni++) {
                    const int gc = colBlock + wn * WTN + ni * 8 + kq * 2;
                    float v0 = acc[mi][ni][half * 2 + 0] + bias[gc];
                    float v1 = acc[mi][ni][half * 2 + 1] + bias[gc + 1];
                    if (MODE == 0) { v0 = fmaxf(v0, 0.0f); v1 = fmaxf(v1, 0.0f); }
                    const size_t base = (size_t)grow * NOUT + gc;
                    if (MODE == 0 || z == 0) {
                        __half* oh = Oh;
                        if (MODE == 0) oh += (size_t)z * OZ;
                        *reinterpret_cast<__half2*>(oh + base) =
                            __halves2half2(__float2half(v0), __float2half(v1));
                    } else {
                        *reinterpret_cast<float2*>(Ofa + base) = make_float2(v0, v1);
                    }
                }
            }
        }
    }
}

// ---------------------------------------------------------------------------
// Unified prep kernel (identical to the 41.8us version)
// ---------------------------------------------------------------------------
#define XB 2048
#define WF_TILES 512
#define WB_TILES 256
#define WO_BLKS 64
#define OI_BLKS 4

__device__ __forceinline__ void transpose_tile(
    const float* __restrict__ W, __half* __restrict__ hi,
    int Krows, int Ncols, int bxn, int byk, float (*tile)[33], int tid)
{
    int tx = tid & 31, ty = tid >> 5;
    int n0 = bxn * 32, k0 = byk * 32;
    #pragma unroll
    for (int i = 0; i < 32; i += 8)
        tile[ty + i][tx] = W[(size_t)(k0 + ty + i) * Ncols + n0 + tx];
    __syncthreads();
    #pragma unroll
    for (int i = 0; i < 32; i += 8)
        hi[(size_t)(n0 + ty + i) * Krows + k0 + tx] = __float2half(tile[tx][ty + i]);
}

__global__ void __launch_bounds__(256)
prep_kernel(const float* __restrict__ x0, const float* __restrict__ x1,
            const float* __restrict__ W_feat,
            const float* __restrict__ W_br0, const float* __restrict__ W_br1,
            const float* __restrict__ W_out, const float* __restrict__ b_out,
            __half* __restrict__ X,
            __half* __restrict__ Wf, __half* __restrict__ Wb,
            __half* __restrict__ Wo, float* __restrict__ out)
{
    __shared__ float tile[32][33];
    const int tid = threadIdx.x;
    int bx = blockIdx.x;

    if (bx < 2 * XB) {
        const float* src = (bx < XB) ? x0 : x1;
        size_t zoff = (bx < XB) ? 0 : (size_t)BATCH * IN_DIM;
        int i = (bx & (XB - 1)) * 256 + tid;
        float4 v = reinterpret_cast<const float4*>(src)[i];
        __half2* hp = reinterpret_cast<__half2*>(X + zoff) + (size_t)i * 2;
        hp[0] = __halves2half2(__float2half(v.x), __float2half(v.y));
        hp[1] = __halves2half2(__float2half(v.z), __float2half(v.w));
    } else if (bx < 2 * XB + WF_TILES) {
        int t = bx - 2 * XB;
        transpose_tile(W_feat, Wf, IN_DIM, HID, t & 15, t >> 4, tile, tid);
    } else if (bx < 2 * XB + WF_TILES + WB_TILES) {
        int t = bx - (2 * XB + WF_TILES);
        int zz = t >> 7; t &= 127;
        transpose_tile(zz ? W_br1 : W_br0, Wb + (size_t)zz * FEAT * HID,
                       HID, FEAT, t & 7, t >> 3, tile, tid);
    } else if (bx < 2 * XB + WF_TILES + WB_TILES + WO_BLKS) {
        int t = bx - (2 * XB + WF_TILES + WB_TILES);
        int r = t * 1024 + tid * 4;
        #pragma unroll
        for (int q = 0; q < 4; q++) {
            float2 w = reinterpret_cast<const float2*>(W_out)[r + q];
            Wo[r + q]               = __float2half(w.x);
            Wo[FEAT * FEAT + r + q] = __float2half(w.y);
        }
    } else {
        int t = bx - (2 * XB + WF_TILES + WB_TILES + WO_BLKS);
        int i = t * 1024 + tid * 4;
        float b0 = b_out[0], b1 = b_out[1];
        #pragma unroll
        for (int q = 0; q < 4; q++) out[i + q] = ((i + q) & 1) ? b1 : b0;
    }
}

// ---------------------------- launch ----------------------------------------
extern "C" void kernel_launch(void* const* d_in, const int* in_sizes, int n_in,
                              void* d_out, int out_size)
{
    const float* x0     = (const float*)d_in[0];
    const float* x1     = (const float*)d_in[1];
    const float* W_feat = (const float*)d_in[2];
    const float* b_feat = (const float*)d_in[3];
    const float* W_br0  = (const float*)d_in[4];
    const float* b_br0  = (const float*)d_in[5];
    const float* W_br1  = (const float*)d_in[6];
    const float* b_br1  = (const float*)d_in[7];
    const float* W_out  = (const float*)d_in[8];
    const float* b_out  = (const float*)d_in[9];
    float*       out    = (float*)d_out;

    __half *X, *Wf, *Wb, *Wo, *H, *F0;
    float *F1;
    cudaGetSymbolAddress((void**)&X, g_X);
    cudaGetSymbolAddress((void**)&Wf, g_Wf);
    cudaGetSymbolAddress((void**)&Wb, g_Wb);
    cudaGetSymbolAddress((void**)&Wo, g_Wo);
    cudaGetSymbolAddress((void**)&H, g_H);
    cudaGetSymbolAddress((void**)&F0, g_F0);
    cudaGetSymbolAddress((void**)&F1, g_F1);

    // K1:  (64+128)*272*2 = 104448 ; K2/K3: (64+64)*272*2 = 69632
    constexpr int SM1 = 2 * (64 + 128) * 272;
    constexpr int SM2 = 2 * (64 + 64) * 272;
    cudaFuncSetAttribute((const void*)gemm_mma<64, 128, 256, 1024, 512, 0, 2, 4>,
                         cudaFuncAttributeMaxDynamicSharedMemorySize, SM1);
    cudaFuncSetAttribute((const void*)gemm_mma<64, 64, 128, 512, 256, 1, 3, 2>,
                         cudaFuncAttributeMaxDynamicSharedMemorySize, SM2);
    cudaFuncSetAttribute((const void*)gemm_mma<64, 64, 128, 256, 256, 2, 3, 2>,
                         cudaFuncAttributeMaxDynamicSharedMemorySize, SM2);

    prep_kernel<<<2 * XB + WF_TILES + WB_TILES + WO_BLKS + OI_BLKS, 256>>>(
        x0, x1, W_feat, W_br0, W_br1, W_out, b_out, X, Wf, Wb, Wo, out);

    // K1: grid (4, 32, 2) = 256 CTAs x 8 warps; warp tile 32x32 (MI=2, NI=4)
    gemm_mma<64, 128, 256, 1024, 512, 0, 2, 4>
        <<<dim3(HID / 128, BATCH / 64, 2), 256, SM1>>>(
        X, Wf, b_feat, b_feat, H, nullptr, nullptr);

    // K2: grid (4, 32, 2) = 256 CTAs x 4 warps; warp tile 32x32 (MI=2, NI=4)
    gemm_mma<64, 64, 128, 512, 256, 1, 3, 2>
        <<<dim3(FEAT / 64, BATCH / 64, 2), 128, SM2>>>(
        H, Wb, b_br0, b_br1, F0, F1, nullptr);

    // K3 (+fused K4): grid (4, 32, 2) = 256 CTAs x 4 warps; warp tile 32x32
    gemm_mma<64, 64, 128, 256, 256, 2, 3, 2>
        <<<dim3(FEAT / 64, BATCH / 64, 2), 128, SM2>>>(
        F0, Wo, nullptr, nullptr, nullptr, F1, out);
}

// round 16
// speedup vs baseline: 1.4622x; 1.0292x over previous
#include <cuda_runtime.h>
#include <cuda_fp16.h>
#include <cstdint>

#define BATCH   2048
#define IN_DIM  1024
#define HID     512
#define FEAT    256

// ---------------------------------------------------------------------------
// helpers
// ---------------------------------------------------------------------------
__device__ __forceinline__ uint32_t smem_u32(const void* p) {
    uint32_t a;
    asm("{ .reg .u64 t; cvta.to.shared.u64 t, %1; cvt.u32.u64 %0, t; }"
        : "=r"(a) : "l"(p));
    return a;
}

__device__ __forceinline__ void mma16816(float* c, const uint32_t* a, const uint32_t* b)
{
    asm volatile(
        "mma.sync.aligned.m16n8k16.row.col.f32.f16.f16.f32 "
        "{%0,%1,%2,%3}, {%4,%5,%6,%7}, {%8,%9}, {%0,%1,%2,%3};\n"
        : "+f"(c[0]), "+f"(c[1]), "+f"(c[2]), "+f"(c[3])
        : "r"(a[0]), "r"(a[1]), "r"(a[2]), "r"(a[3]), "r"(b[0]), "r"(b[1]));
}

#define LDSM4(r0, r1, r2, r3, addr)                                            \
    asm volatile("ldmatrix.sync.aligned.m8n8.x4.shared.b16 {%0,%1,%2,%3}, [%4];" \
        : "=r"(r0), "=r"(r1), "=r"(r2), "=r"(r3) : "r"(addr))

#define CP16(dst, src)                                                         \
    asm volatile("cp.async.cg.shared.global [%0], [%1], 16;"                   \
        :: "r"(dst), "l"(src))
#define CP_COMMIT() asm volatile("cp.async.commit_group;" ::: "memory")
#define CP_WAIT1()  asm volatile("cp.async.wait_group 1;" ::: "memory")
#define CP_WAIT0()  asm volatile("cp.async.wait_group 0;" ::: "memory")

// ---------------------------- scratch ---------------------------------------
__device__ __align__(16) __half g_X[2 * BATCH * IN_DIM];      // fp16 x
__device__ __align__(16) __half g_Wf[HID * IN_DIM];           // [N=512][K=1024]
__device__ __align__(16) __half g_Wb[2 * FEAT * HID];         // [z][N=256][K=512]
__device__ __align__(16) __half g_Wo[2 * FEAT * FEAT];        // [o][j][i]
__device__ __align__(16) __half g_H[2 * BATCH * HID];
__device__ __align__(16) __half g_F0[BATCH * FEAT];
__device__ __align__(16) float  g_F1[BATCH * FEAT];

// ---------------------------------------------------------------------------
// fp16 mma.sync GEMM, BK=128 double buffer.
// Warp tile 64x32: MI=4, NI=4 -> 16 independent MMAs per ks-step per warp.
// MODE 0: K1 (bias+relu, fp16 out)
// MODE 1: K2 (bias; z=0 -> fp16 F0, z=1 -> fp32 F1)
// MODE 2: K3 (fused final dot into out via atomics)
// ---------------------------------------------------------------------------
template <int BM, int BN, int THREADS, int KK, int NOUT, int MODE, int MINB, int WNW>
__global__ void __launch_bounds__(THREADS, MINB)
gemm_mma(const __half* __restrict__ A, const __half* __restrict__ B,
         const float* __restrict__ bias0, const float* __restrict__ bias1,
         __half* __restrict__ Oh, float* __restrict__ Ofa, float* __restrict__ Ofb)
{
    constexpr int BK   = 128;
    constexpr int CHNK = BK / 8;              // 16
    constexpr int ROWB = BK * 2 + 16;         // 272
    constexpr int T    = KK / BK;
    constexpr int WARPS = THREADS / 32;
    constexpr int WN_W = WNW;
    constexpr int WM_W = WARPS / WN_W;
    constexpr int WTM  = BM / WM_W;           // 64
    constexpr int WTN  = BN / WN_W;           // 32
    constexpr int MI   = WTM / 16;            // 4
    constexpr int NI   = WTN / 8;             // 4
    constexpr int STAGE = (BM + BN) * ROWB;
    constexpr size_t AZ = (MODE == 0) ? (size_t)BATCH * IN_DIM
                         : (MODE == 1) ? (size_t)BATCH * HID : 0;
    constexpr size_t BZ = (MODE == 0) ? 0
                         : (MODE == 1) ? (size_t)FEAT * HID : (size_t)FEAT * FEAT;
    constexpr size_t OZ = (size_t)BATCH * NOUT;

    extern __shared__ char dsm[];
    const uint32_t sbase = smem_u32(dsm);

    const int tid  = threadIdx.x;
    const int lane = tid & 31;
    const int warp = tid >> 5;
    const int wm = warp / WN_W, wn = warp % WN_W;
    const int z = blockIdx.z;
    const int rowBlock = blockIdx.y * BM;
    const int colBlock = blockIdx.x * BN;

    A += (size_t)z * AZ;
    B += (size_t)z * BZ;
    const float* bias = z ? bias1 : bias0;

    auto stage = [&](int t, int buf_i) {
        const int kt = t * BK;
        const uint32_t buf = sbase + buf_i * STAGE;
        #pragma unroll
        for (int i = 0; i < BM * CHNK / THREADS; i++) {
            int slot = tid + i * THREADS;
            int row = slot / CHNK, ch = slot % CHNK;
            CP16(buf + row * ROWB + ch * 16,
                 A + (size_t)(rowBlock + row) * KK + kt + ch * 8);
        }
        #pragma unroll
        for (int i = 0; i < BN * CHNK / THREADS; i++) {
            int slot = tid + i * THREADS;
            int row = slot / CHNK, ch = slot % CHNK;
            CP16(buf + (BM + row) * ROWB + ch * 16,
                 B + (size_t)(colBlock + row) * KK + kt + ch * 8);
        }
        CP_COMMIT();
    };

    float acc[MI][NI][4];
    #pragma unroll
    for (int mi = 0; mi < MI; mi++)
        #pragma unroll
        for (int ni = 0; ni < NI; ni++)
            #pragma unroll
            for (int r = 0; r < 4; r++) acc[mi][ni][r] = 0.0f;

    const uint32_t aOff = (uint32_t)((wm * WTM + (lane & 15)) * ROWB + (lane >> 4) * 16);
    const uint32_t bOff = (uint32_t)((wn * WTN + ((lane >> 4) << 3) + (lane & 7)) * ROWB
                                     + ((lane >> 3) & 1) * 16);

    stage(0, 0);
    if (T > 1) stage(1, 1);

    #pragma unroll 1
    for (int t = 0; t < T; t++) {
        if (t + 1 < T) { CP_WAIT1(); } else { CP_WAIT0(); }
        __syncthreads();

        const uint32_t buf = sbase + (t & 1) * STAGE;
        const uint32_t aB = buf + aOff;
        const uint32_t bB = buf + BM * ROWB + bOff;

        #pragma unroll
        for (int ks = 0; ks < BK / 16; ks++) {
            const uint32_t ko = ks * 32;
            uint32_t ah[MI][4];
            #pragma unroll
            for (int mi = 0; mi < MI; mi++)
                LDSM4(ah[mi][0], ah[mi][1], ah[mi][2], ah[mi][3],
                      aB + mi * 16 * ROWB + ko);
            uint32_t bh[NI][2];
            #pragma unroll
            for (int np = 0; np < NI / 2; np++)
                LDSM4(bh[np * 2][0], bh[np * 2][1], bh[np * 2 + 1][0], bh[np * 2 + 1][1],
                      bB + np * 16 * ROWB + ko);
            #pragma unroll
            for (int mi = 0; mi < MI; mi++)
                #pragma unroll
                for (int ni = 0; ni < NI; ni++)
                    mma16816(acc[mi][ni], ah[mi], bh[ni]);
        }

        if (t + 2 < T) {
            __syncthreads();
            stage(t + 2, t & 1);
        }
    }

    // ------------------------------ epilogue --------------------------------
    const int g  = lane >> 2;
    const int kq = lane & 3;
    #pragma unroll
    for (int mi = 0; mi < MI; mi++) {
        #pragma unroll
        for (int half = 0; half < 2; half++) {
            const int grow = rowBlock + wm * WTM + mi * 16 + half * 8 + g;
            if (MODE == 2) {
                const float* F1p = Ofa;
                float s = 0.0f;
                #pragma unroll
                for (int ni = 0; ni < NI; ni++) {
                    const int gc = colBlock + wn * WTN + ni * 8 + kq * 2;
                    float2 fv = *reinterpret_cast<const float2*>(
                        F1p + (size_t)grow * FEAT + gc);
                    s = fmaf(acc[mi][ni][half * 2 + 0], fv.x,
                        fmaf(acc[mi][ni][half * 2 + 1], fv.y, s));
                }
                s += __shfl_xor_sync(0xFFFFFFFFu, s, 1);
                s += __shfl_xor_sync(0xFFFFFFFFu, s, 2);
                if (kq == 0) atomicAdd(&Ofb[grow * 2 + z], s);
            } else {
                #pragma unroll
                for (int ni = 0; ni < NI; ni++) {
                    const int gc = colBlock + wn * WTN + ni * 8 + kq * 2;
                    float v0 = acc[mi][ni][half * 2 + 0] + bias[gc];
                    float v1 = acc[mi][ni][half * 2 + 1] + bias[gc + 1];
                    if (MODE == 0) { v0 = fmaxf(v0, 0.0f); v1 = fmaxf(v1, 0.0f); }
                    const size_t base = (size_t)grow * NOUT + gc;
                    if (MODE == 0 || z == 0) {
                        __half* oh = Oh;
                        if (MODE == 0) oh += (size_t)z * OZ;
                        *reinterpret_cast<__half2*>(oh + base) =
                            __halves2half2(__float2half(v0), __float2half(v1));
                    } else {
                        *reinterpret_cast<float2*>(Ofa + base) = make_float2(v0, v1);
                    }
                }
            }
        }
    }
}

// ---------------------------------------------------------------------------
// Unified prep kernel (unchanged)
// ---------------------------------------------------------------------------
#define XB 2048
#define WF_TILES 512
#define WB_TILES 256
#define WO_BLKS 64
#define OI_BLKS 4

__device__ __forceinline__ void transpose_tile(
    const float* __restrict__ W, __half* __restrict__ hi,
    int Krows, int Ncols, int bxn, int byk, float (*tile)[33], int tid)
{
    int tx = tid & 31, ty = tid >> 5;
    int n0 = bxn * 32, k0 = byk * 32;
    #pragma unroll
    for (int i = 0; i < 32; i += 8)
        tile[ty + i][tx] = W[(size_t)(k0 + ty + i) * Ncols + n0 + tx];
    __syncthreads();
    #pragma unroll
    for (int i = 0; i < 32; i += 8)
        hi[(size_t)(n0 + ty + i) * Krows + k0 + tx] = __float2half(tile[tx][ty + i]);
}

__global__ void __launch_bounds__(256)
prep_kernel(const float* __restrict__ x0, const float* __restrict__ x1,
            const float* __restrict__ W_feat,
            const float* __restrict__ W_br0, const float* __restrict__ W_br1,
            const float* __restrict__ W_out, const float* __restrict__ b_out,
            __half* __restrict__ X,
            __half* __restrict__ Wf, __half* __restrict__ Wb,
            __half* __restrict__ Wo, float* __restrict__ out)
{
    __shared__ float tile[32][33];
    const int tid = threadIdx.x;
    int bx = blockIdx.x;

    if (bx < 2 * XB) {
        const float* src = (bx < XB) ? x0 : x1;
        size_t zoff = (bx < XB) ? 0 : (size_t)BATCH * IN_DIM;
        int i = (bx & (XB - 1)) * 256 + tid;
        float4 v = reinterpret_cast<const float4*>(src)[i];
        __half2* hp = reinterpret_cast<__half2*>(X + zoff) + (size_t)i * 2;
        hp[0] = __halves2half2(__float2half(v.x), __float2half(v.y));
        hp[1] = __halves2half2(__float2half(v.z), __float2half(v.w));
    } else if (bx < 2 * XB + WF_TILES) {
        int t = bx - 2 * XB;
        transpose_tile(W_feat, Wf, IN_DIM, HID, t & 15, t >> 4, tile, tid);
    } else if (bx < 2 * XB + WF_TILES + WB_TILES) {
        int t = bx - (2 * XB + WF_TILES);
        int zz = t >> 7; t &= 127;
        transpose_tile(zz ? W_br1 : W_br0, Wb + (size_t)zz * FEAT * HID,
                       HID, FEAT, t & 7, t >> 3, tile, tid);
    } else if (bx < 2 * XB + WF_TILES + WB_TILES + WO_BLKS) {
        int t = bx - (2 * XB + WF_TILES + WB_TILES);
        int r = t * 1024 + tid * 4;
        #pragma unroll
        for (int q = 0; q < 4; q++) {
            float2 w = reinterpret_cast<const float2*>(W_out)[r + q];
            Wo[r + q]               = __float2half(w.x);
            Wo[FEAT * FEAT + r + q] = __float2half(w.y);
        }
    } else {
        int t = bx - (2 * XB + WF_TILES + WB_TILES + WO_BLKS);
        int i = t * 1024 + tid * 4;
        float b0 = b_out[0], b1 = b_out[1];
        #pragma unroll
        for (int q = 0; q < 4; q++) out[i + q] = ((i + q) & 1) ? b1 : b0;
    }
}

// ---------------------------- launch ----------------------------------------
extern "C" void kernel_launch(void* const* d_in, const int* in_sizes, int n_in,
                              void* d_out, int out_size)
{
    const float* x0     = (const float*)d_in[0];
    const float* x1     = (const float*)d_in[1];
    const float* W_feat = (const float*)d_in[2];
    const float* b_feat = (const float*)d_in[3];
    const float* W_br0  = (const float*)d_in[4];
    const float* b_br0  = (const float*)d_in[5];
    const float* W_br1  = (const float*)d_in[6];
    const float* b_br1  = (const float*)d_in[7];
    const float* W_out  = (const float*)d_in[8];
    const float* b_out  = (const float*)d_in[9];
    float*       out    = (float*)d_out;

    __half *X, *Wf, *Wb, *Wo, *H, *F0;
    float *F1;
    cudaGetSymbolAddress((void**)&X, g_X);
    cudaGetSymbolAddress((void**)&Wf, g_Wf);
    cudaGetSymbolAddress((void**)&Wb, g_Wb);
    cudaGetSymbolAddress((void**)&Wo, g_Wo);
    cudaGetSymbolAddress((void**)&H, g_H);
    cudaGetSymbolAddress((void**)&F0, g_F0);
    cudaGetSymbolAddress((void**)&F1, g_F1);

    // all kernels: stage (128+64)*272 = 52224 ; x2 = 104448
    constexpr int SM = 2 * (128 + 64) * 272;
    cudaFuncSetAttribute((const void*)gemm_mma<128, 64, 128, 1024, 512, 0, 1, 2>,
                         cudaFuncAttributeMaxDynamicSharedMemorySize, SM);
    cudaFuncSetAttribute((const void*)gemm_mma<128, 64, 128, 512, 256, 1, 1, 2>,
                         cudaFuncAttributeMaxDynamicSharedMemorySize, SM);
    cudaFuncSetAttribute((const void*)gemm_mma<128, 64, 128, 256, 256, 2, 1, 2>,
                         cudaFuncAttributeMaxDynamicSharedMemorySize, SM);

    prep_kernel<<<2 * XB + WF_TILES + WB_TILES + WO_BLKS + OI_BLKS, 256>>>(
        x0, x1, W_feat, W_br0, W_br1, W_out, b_out, X, Wf, Wb, Wo, out);

    // K1: grid (8, 16, 2) = 256 CTAs x 4 warps; warp tile 64x32 (MI=4, NI=4)
    gemm_mma<128, 64, 128, 1024, 512, 0, 1, 2>
        <<<dim3(HID / 64, BATCH / 128, 2), 128, SM>>>(
        X, Wf, b_feat, b_feat, H, nullptr, nullptr);

    // K2: grid (4, 16, 2) = 128 CTAs x 4 warps; warp tile 64x32
    gemm_mma<128, 64, 128, 512, 256, 1, 1, 2>
        <<<dim3(FEAT / 64, BATCH / 128, 2), 128, SM>>>(
        H, Wb, b_br0, b_br1, F0, F1, nullptr);

    // K3 (+fused K4): grid (4, 16, 2) = 128 CTAs x 4 warps; warp tile 64x32
    gemm_mma<128, 64, 128, 256, 256, 2, 1, 2>
        <<<dim3(FEAT / 64, BATCH / 128, 2), 128, SM>>>(
        F0, Wo, nullptr, nullptr, nullptr, F1, out);
}